// round 12
// baseline (speedup 1.0000x reference)
#include <cuda_runtime.h>
#include <math.h>

#define BATCH 32
#define NCLS 3
#define HH 192
#define WW 640
#define HW (HH*WW)
#define NPL (BATCH*NCLS)
#define KTOP 50
#define NEG_INF -3.402823466e38f
#define PI_F 3.14159265358979f
#define DET_THR 0.25f
#define HI_THR 0.999f
#define RROWS 8
#define NYB (HH/RROWS)
#define TCAP 8
#define NTHR 160
#define HCAP 2048
#define CCAP 2048

typedef unsigned long long u64;
typedef unsigned int u32;

// -------- scratch (static device globals; zero-initialized at load) --------
__device__ int g_count[NPL];
__device__ int g_hicnt[BATCH];
__device__ u64 g_ckey[NPL][HW];          // full per-plane lists (exact fallback)
__device__ u64 g_hikey[BATCH][HCAP];     // per-batch hi tier (v > HI_THR), cls pre-packed

__constant__ float c_dimref[3][3] = {
    {3.88f, 1.63f, 1.53f},
    {0.84f, 1.76f, 0.66f},
    {1.78f, 1.52f, 1.78f}};

__device__ __forceinline__ float max3(float a, float b, float c) {
    return fmaxf(a, fmaxf(b, c));
}
__device__ __forceinline__ u64 pack_key(float v, int idx) {
    return ((u64)__float_as_uint(v) << 32) | (u32)(~idx);
}
// final key: val<<32 | ~((cls<<17)|idx) — monotonic in (val desc, cls asc, idx asc)
__device__ __forceinline__ u64 repack(u64 k, int c) {
    int idx = (int)(~(u32)k) & 0x1FFFF;
    return (k & 0xFFFFFFFF00000000ULL) | (u32)(~((c << 17) | idx));
}

// -------- pass 1: 3x3 NMS, load-all-then-compute (MLP=10) --------
__global__ __launch_bounds__(NTHR) void k_nms(const float* __restrict__ heat) {
    int plane = blockIdx.y;
    int batch = plane / NCLS;
    int cls   = plane - batch * NCLS;
    int tid = threadIdx.x;
    int warp = tid >> 5, lane = tid & 31;
    int xb = warp * 128 + lane * 4;
    int y0 = blockIdx.x * RROWS;
    const float* p = heat + (size_t)plane * HW + xb;

    const float4 NEG4 = make_float4(NEG_INF, NEG_INF, NEG_INF, NEG_INF);

    __shared__ float sL[5][RROWS];
    __shared__ float sR[5][RROWS];
    __shared__ u64 sbuf[TCAP][NTHR];
    __shared__ int wtot[5], spref[5];
    __shared__ int sgbase;

    float4 r[RROWS + 2];
    const float* rp = p + (y0 - 1) * WW;
#pragma unroll
    for (int k = 0; k < RROWS + 2; k++) {
        int y = y0 - 1 + k;
        r[k] = (y >= 0 && y < HH) ? *(const float4*)(rp + k * WW) : NEG4;
    }

    float4 cm[RROWS];
#pragma unroll
    for (int i = 0; i < RROWS; i++) {
        cm[i].x = max3(r[i].x, r[i+1].x, r[i+2].x);
        cm[i].y = max3(r[i].y, r[i+1].y, r[i+2].y);
        cm[i].z = max3(r[i].z, r[i+1].z, r[i+2].z);
        cm[i].w = max3(r[i].w, r[i+1].w, r[i+2].w);
    }

    if (lane == 31) {
#pragma unroll
        for (int i = 0; i < RROWS; i++) sL[warp][i] = cm[i].w;
    }
    if (lane == 0) {
#pragma unroll
        for (int i = 0; i < RROWS; i++) sR[warp][i] = cm[i].x;
    }
    __syncthreads();

    int cnt = 0;
#pragma unroll
    for (int i = 0; i < RROWS; i++) {
        float left = __shfl_up_sync(0xffffffffu, cm[i].w, 1);
        if (lane == 0) left = (warp > 0) ? sL[warp - 1][i] : NEG_INF;
        float right = __shfl_down_sync(0xffffffffu, cm[i].x, 1);
        if (lane == 31) right = (warp < 4) ? sR[warp + 1][i] : NEG_INF;

        float h0 = max3(left,    cm[i].x, cm[i].y);
        float h1 = max3(cm[i].x, cm[i].y, cm[i].z);
        float h2 = max3(cm[i].y, cm[i].z, cm[i].w);
        float h3 = max3(cm[i].z, cm[i].w, right);

        float4 b = r[i + 1];
        int bi = (y0 + i) * WW + xb;
        if (h0 == b.x && b.x > DET_THR && cnt < TCAP) sbuf[cnt++][tid] = pack_key(b.x, bi);
        if (h1 == b.y && b.y > DET_THR && cnt < TCAP) sbuf[cnt++][tid] = pack_key(b.y, bi + 1);
        if (h2 == b.z && b.z > DET_THR && cnt < TCAP) sbuf[cnt++][tid] = pack_key(b.z, bi + 2);
        if (h3 == b.w && b.w > DET_THR && cnt < TCAP) sbuf[cnt++][tid] = pack_key(b.w, bi + 3);
    }

    // hi tier: duplicate survivors with v > HI_THR into per-batch array,
    // cls pre-packed (expected ~125/plane -> ~5 atomics/block)
    const u64 hi_min = ((u64)__float_as_uint(HI_THR)) << 32;
    for (int j = 0; j < cnt; j++) {
        u64 k = sbuf[j][tid];
        if (k > hi_min) {
            int hp = atomicAdd(&g_hicnt[batch], 1);
            if (hp < HCAP) g_hikey[batch][hp] = repack(k, cls);
        }
    }

    int x = cnt;
#pragma unroll
    for (int off = 1; off < 32; off <<= 1) {
        int yv = __shfl_up_sync(0xffffffffu, x, off);
        if (lane >= off) x += yv;
    }
    int excl = x - cnt;
    if (lane == 31) wtot[warp] = x;
    __syncthreads();
    if (tid == 0) {
        int s = 0;
#pragma unroll
        for (int w = 0; w < 5; w++) { spref[w] = s; s += wtot[w]; }
        sgbase = (s > 0) ? atomicAdd(&g_count[plane], s) : 0;
    }
    __syncthreads();
    int base = sgbase + spref[warp] + excl;
    for (int j = 0; j < cnt; j++)
        g_ckey[plane][base + j] = sbuf[j][tid];
}

// -------- pass 2: per-batch top-50 + detection math --------
__device__ __forceinline__ void inv3(const float* M, float* R) {
    float a = M[0], b = M[1], c = M[2];
    float d = M[3], e = M[4], f = M[5];
    float g = M[6], h = M[7], i = M[8];
    float A = e * i - f * h;
    float Bm = -(d * i - f * g);
    float C = d * h - e * g;
    float det = a * A + b * Bm + c * C;
    float id = 1.0f / det;
    R[0] = A * id;  R[1] = -(b * i - c * h) * id;  R[2] = (b * f - c * e) * id;
    R[3] = Bm * id; R[4] = (a * i - c * g) * id;   R[5] = -(a * f - c * d) * id;
    R[6] = C * id;  R[7] = -(a * h - b * g) * id;  R[8] = (a * e - b * d) * id;
}
__device__ __forceinline__ int vbucket(u64 k) {
    int bkt = (int)(((u32)(k >> 32) - 0x3e800000u) >> 14);
    return (bkt > 1023) ? 1023 : bkt;
}

__global__ __launch_bounds__(1024) void k_select(
        const float* __restrict__ reg, const float* __restrict__ tmat,
        const float* __restrict__ Kmat, const float* __restrict__ img,
        float* __restrict__ out) {
    int b = blockIdx.x;
    int tid = threadIdx.x;

    __shared__ int hist[1024];
    __shared__ u64 cand[CCAP + 8];
    __shared__ u64 wtop[KTOP];
    __shared__ int sn[NCLS];
    __shared__ int sB, scc, shic;

    if (tid < NCLS) {
        sn[tid] = g_count[b * NCLS + tid];
        g_count[b * NCLS + tid] = 0;      // reset for next graph replay
    }
    if (tid == 0) {
        shic = g_hicnt[b];
        g_hicnt[b] = 0;
        scc = 0;
    }
    if (tid < KTOP) wtop[tid] = 0;
    __syncthreads();

    int hic = shic;
    int m;

    if (hic >= KTOP && hic <= HCAP && hic <= CCAP) {
        // ---- fast path: top-50 is contained in the hi tier (it holds ALL
        // candidates with v > HI_THR; there are >= KTOP of them) ----
        m = hic;
        for (int i = tid; i < m; i += 1024)
            cand[i] = g_hikey[b][i];
    } else {
        // ---- exact fallback: histogram select over full per-plane lists ----
        hist[tid] = 0;
        __syncthreads();
#pragma unroll
        for (int c = 0; c < NCLS; c++) {
            const u64* ck = g_ckey[b * NCLS + c];
            int n = sn[c];
            int i = tid;
            for (; i + 7 * 1024 < n; i += 8 * 1024) {
                u64 kk[8];
#pragma unroll
                for (int j = 0; j < 8; j++) kk[j] = ck[i + j * 1024];
#pragma unroll
                for (int j = 0; j < 8; j++) atomicAdd(&hist[vbucket(kk[j])], 1);
            }
            for (; i < n; i += 1024)
                atomicAdd(&hist[vbucket(ck[i])], 1);
        }
        __syncthreads();
        if (tid == 0) {
            int cum = 0, bsel = 0;
            for (int bkt = 1023; bkt >= 0; bkt--) {
                cum += hist[bkt];
                if (cum >= KTOP) { bsel = bkt; break; }
            }
            sB = bsel;
        }
        __syncthreads();
        u64 kmin = ((u64)(0x3e800000u + ((u32)sB << 14))) << 32;
#pragma unroll
        for (int c = 0; c < NCLS; c++) {
            const u64* ck = g_ckey[b * NCLS + c];
            int n = sn[c];
            for (int i = tid; i < n; i += 1024) {
                u64 k = ck[i];
                if (k >= kmin) {
                    int pos = atomicAdd(&scc, 1);
                    if (pos < CCAP) cand[pos] = repack(k, c);
                }
            }
        }
        __syncthreads();
        m = min(scc, CCAP);
    }

    // zero-pad to a multiple of 8 (pad keys = 0, never counted: real keys > 0)
    int m8 = (m + 7) & ~7;
    if (tid >= m && tid < m8) cand[tid] = 0;
    if (tid < 8) cand[m8 + tid] = 0;
    __syncthreads();

    // ---- brute-force stable rank, 8 LDS in flight per iteration ----
    if (tid < m) {
        u64 k = cand[tid];
        int rank = 0;
        for (int j = 0; j < m8; j += 8) {
            u64 c0 = cand[j + 0], c1 = cand[j + 1], c2 = cand[j + 2], c3 = cand[j + 3];
            u64 c4 = cand[j + 4], c5 = cand[j + 5], c6 = cand[j + 6], c7 = cand[j + 7];
            rank += (int)(c0 > k) + (int)(c1 > k) + (int)(c2 > k) + (int)(c3 > k)
                  + (int)(c4 > k) + (int)(c5 > k) + (int)(c6 > k) + (int)(c7 > k);
        }
        if (rank < KTOP) wtop[rank] = k;
    }
    __syncthreads();

    if (tid >= KTOP) return;

    u64 key = wtop[tid];
    float score = __uint_as_float((u32)(key >> 32));
    float* o = out + ((size_t)b * KTOP + tid) * 14;

    if (!(score > DET_THR)) {      // includes zero-padding keys
#pragma unroll
        for (int k = 0; k < 14; k++) o[k] = 0.0f;
        return;
    }

    u32 low = ~(u32)key;
    int cls = (int)(low >> 17);
    int ind = (int)(low & 0x1FFFF);
    float xs = (float)(ind % WW);
    float ys = (float)(ind / WW);

    float r8[8];
#pragma unroll
    for (int ch = 0; ch < 8; ch++)
        r8[ch] = reg[((size_t)b * 8 + ch) * HW + ind];

    float T[9], Ti[9], Kk[9], Ki[9];
#pragma unroll
    for (int k = 0; k < 9; k++) { T[k] = tmat[b * 9 + k]; Kk[k] = Kmat[b * 9 + k]; }
    inv3(T, Ti);
    inv3(Kk, Ki);

    float px = xs + r8[1];
    float py = ys + r8[2];
    float pix = Ti[0] * px + Ti[1] * py + Ti[2];
    float piy = Ti[3] * px + Ti[4] * py + Ti[5];
    float piz = Ti[6] * px + Ti[7] * py + Ti[8];

    float depth = r8[0] * 16.32f + 28.01f;
    float vx = pix * depth, vy = piy * depth, vz = piz * depth;
    float lx = Ki[0] * vx + Ki[1] * vy + Ki[2] * vz;
    float ly = Ki[3] * vx + Ki[4] * vy + Ki[5] * vz;
    float lz = Ki[6] * vx + Ki[7] * vy + Ki[8] * vz;

    float d0 = __expf(r8[3]) * c_dimref[cls][0];
    float d1 = __expf(r8[4]) * c_dimref[cls][1];
    float d2 = __expf(r8[5]) * c_dimref[cls][2];
    ly += d1 * 0.5f;

    float rays = atanf(__fdividef(lx, lz + 1e-7f));
    float al = atanf(__fdividef(r8[6], r8[7] + 1e-7f));
    al += (r8[7] >= 0.0f) ? -PI_F * 0.5f : PI_F * 0.5f;
    float roty = al + rays;
    roty = (roty > PI_F) ? roty - 2.0f * PI_F : ((roty < -PI_F) ? roty + 2.0f * PI_F : roty);
    al   = (al   > PI_F) ? al   - 2.0f * PI_F : ((al   < -PI_F) ? al   + 2.0f * PI_F : al);

    const float SX[8] = {-0.5f, 0.5f, 0.5f, 0.5f, 0.5f, -0.5f, -0.5f, -0.5f};
    const float SY[8] = {-1.0f, -1.0f, 0.0f, 0.0f, -1.0f, -1.0f, 0.0f, 0.0f};
    const float SZ[8] = {-0.5f, -0.5f, -0.5f, 0.5f, 0.5f, 0.5f, 0.5f, -0.5f};

    float sr, cr;
    __sincosf(roty, &sr, &cr);
    float umin = 3.4e38f, umax = -3.4e38f, wmin = 3.4e38f, wmax = -3.4e38f;
#pragma unroll
    for (int j = 0; j < 8; j++) {
        float cx = d0 * SX[j], cy = d1 * SY[j], cz = d2 * SZ[j];
        float wx = cr * cx + sr * cz + lx;
        float wy = cy + ly;
        float wz = -sr * cx + cr * cz + lz;
        float qx = Kk[0] * wx + Kk[1] * wy + Kk[2] * wz;
        float qy = Kk[3] * wx + Kk[4] * wy + Kk[5] * wz;
        float qz = Kk[6] * wx + Kk[7] * wy + Kk[8] * wz;
        float rq = __fdividef(1.0f, qz);
        float u = qx * rq;
        float w = qy * rq;
        umin = fminf(umin, u); umax = fmaxf(umax, u);
        wmin = fminf(wmin, w); wmax = fmaxf(wmax, w);
    }

    float Wi = img[b * 2 + 0], Hi = img[b * 2 + 1];
    float xmin = fminf(fmaxf(umin, 0.0f), Wi);
    float ymin = fminf(fmaxf(wmin, 0.0f), Hi);
    float xmax = fminf(fmaxf(umax, 0.0f), Wi);
    float ymax = fminf(fmaxf(wmax, 0.0f), Hi);

    o[0]  = (float)cls;
    o[1]  = al;
    o[2]  = xmin;
    o[3]  = ymin;
    o[4]  = xmax;
    o[5]  = ymax;
    o[6]  = d1;   // dims rolled -1: (d1, d2, d0)
    o[7]  = d2;
    o[8]  = d0;
    o[9]  = lx;
    o[10] = ly;
    o[11] = lz;
    o[12] = roty;
    o[13] = score;
}

extern "C" void kernel_launch(void* const* d_in, const int* in_sizes, int n_in,
                              void* d_out, int out_size) {
    const float* heat = (const float*)d_in[0];
    const float* reg  = (const float*)d_in[1];
    const float* tm   = (const float*)d_in[2];
    const float* Km   = (const float*)d_in[3];
    const float* img  = (const float*)d_in[4];
    float* out = (float*)d_out;

    dim3 g_nms(NYB, NPL);   // 24 x 96
    k_nms<<<g_nms, NTHR>>>(heat);
    k_select<<<BATCH, 1024>>>(reg, tm, Km, img, out);
}

// round 13
// speedup vs baseline: 1.3931x; 1.3931x over previous
#include <cuda_runtime.h>
#include <math.h>

#define BATCH 32
#define NCLS 3
#define HH 192
#define WW 640
#define HW (HH*WW)
#define NPL (BATCH*NCLS)
#define KTOP 50
#define NEG_INF -3.402823466e38f
#define PI_F 3.14159265358979f
#define DET_THR 0.25f
#define HI_THR 0.999f
#define RROWS 8
#define NYB (HH/RROWS)
#define TCAP 8
#define NTHR 160
#define HCAP 1024
#define CCAP 3072

typedef unsigned long long u64;
typedef unsigned int u32;

// -------- scratch (static device globals; zero-initialized at load) --------
__device__ int g_count[NPL];
__device__ int g_hicnt[NPL];
__device__ u64 g_ckey[NPL][HW];          // full candidate list (exact fallback)
__device__ u64 g_hikey[NPL][HCAP];       // duplicates of candidates with v > HI_THR

__constant__ float c_dimref[3][3] = {
    {3.88f, 1.63f, 1.53f},
    {0.84f, 1.76f, 0.66f},
    {1.78f, 1.52f, 1.78f}};

__device__ __forceinline__ float max3(float a, float b, float c) {
    return fmaxf(a, fmaxf(b, c));
}
__device__ __forceinline__ u64 pack_key(float v, int idx) {
    return ((u64)__float_as_uint(v) << 32) | (u32)(~idx);
}

// -------- pass 1: 3x3 NMS, load-all-then-compute (MLP=10) --------
__global__ __launch_bounds__(NTHR) void k_nms(const float* __restrict__ heat) {
    int plane = blockIdx.y;
    int tid = threadIdx.x;
    int warp = tid >> 5, lane = tid & 31;
    int xb = warp * 128 + lane * 4;
    int y0 = blockIdx.x * RROWS;
    const float* p = heat + (size_t)plane * HW + xb;

    const float4 NEG4 = make_float4(NEG_INF, NEG_INF, NEG_INF, NEG_INF);

    __shared__ float sL[5][RROWS];
    __shared__ float sR[5][RROWS];
    __shared__ u64 sbuf[TCAP][NTHR];
    __shared__ int wtot[5], spref[5];
    __shared__ int sgbase;

    float4 r[RROWS + 2];
    const float* rp = p + (y0 - 1) * WW;
#pragma unroll
    for (int k = 0; k < RROWS + 2; k++) {
        int y = y0 - 1 + k;
        r[k] = (y >= 0 && y < HH) ? *(const float4*)(rp + k * WW) : NEG4;
    }

    float4 cm[RROWS];
#pragma unroll
    for (int i = 0; i < RROWS; i++) {
        cm[i].x = max3(r[i].x, r[i+1].x, r[i+2].x);
        cm[i].y = max3(r[i].y, r[i+1].y, r[i+2].y);
        cm[i].z = max3(r[i].z, r[i+1].z, r[i+2].z);
        cm[i].w = max3(r[i].w, r[i+1].w, r[i+2].w);
    }

    if (lane == 31) {
#pragma unroll
        for (int i = 0; i < RROWS; i++) sL[warp][i] = cm[i].w;
    }
    if (lane == 0) {
#pragma unroll
        for (int i = 0; i < RROWS; i++) sR[warp][i] = cm[i].x;
    }
    __syncthreads();

    int cnt = 0;
#pragma unroll
    for (int i = 0; i < RROWS; i++) {
        float left = __shfl_up_sync(0xffffffffu, cm[i].w, 1);
        if (lane == 0) left = (warp > 0) ? sL[warp - 1][i] : NEG_INF;
        float right = __shfl_down_sync(0xffffffffu, cm[i].x, 1);
        if (lane == 31) right = (warp < 4) ? sR[warp + 1][i] : NEG_INF;

        float h0 = max3(left,    cm[i].x, cm[i].y);
        float h1 = max3(cm[i].x, cm[i].y, cm[i].z);
        float h2 = max3(cm[i].y, cm[i].z, cm[i].w);
        float h3 = max3(cm[i].z, cm[i].w, right);

        float4 b = r[i + 1];
        int bi = (y0 + i) * WW + xb;
        if (h0 == b.x && b.x > DET_THR && cnt < TCAP) sbuf[cnt++][tid] = pack_key(b.x, bi);
        if (h1 == b.y && b.y > DET_THR && cnt < TCAP) sbuf[cnt++][tid] = pack_key(b.y, bi + 1);
        if (h2 == b.z && b.z > DET_THR && cnt < TCAP) sbuf[cnt++][tid] = pack_key(b.z, bi + 2);
        if (h3 == b.w && b.w > DET_THR && cnt < TCAP) sbuf[cnt++][tid] = pack_key(b.w, bi + 3);
    }

    // hi-tier duplicate: survivors with v > HI_THR (expected ~125/plane)
    const u64 hi_min = ((u64)__float_as_uint(HI_THR)) << 32;
    for (int j = 0; j < cnt; j++) {
        u64 k = sbuf[j][tid];
        if (k > hi_min) {
            int hp = atomicAdd(&g_hicnt[plane], 1);
            if (hp < HCAP) g_hikey[plane][hp] = k;
        }
    }

    int x = cnt;
#pragma unroll
    for (int off = 1; off < 32; off <<= 1) {
        int yv = __shfl_up_sync(0xffffffffu, x, off);
        if (lane >= off) x += yv;
    }
    int excl = x - cnt;
    if (lane == 31) wtot[warp] = x;
    __syncthreads();
    if (tid == 0) {
        int s = 0;
#pragma unroll
        for (int w = 0; w < 5; w++) { spref[w] = s; s += wtot[w]; }
        sgbase = (s > 0) ? atomicAdd(&g_count[plane], s) : 0;
    }
    __syncthreads();
    int base = sgbase + spref[warp] + excl;
    for (int j = 0; j < cnt; j++)
        g_ckey[plane][base + j] = sbuf[j][tid];
}

// -------- pass 2: per-batch top-50 + detection math --------
// Fast path: if >=KTOP candidates have v > HI_THR (and no hi overflow), the
// top-50 is contained in the hi tier (it holds ALL keys above HI_THR).
// Fallback (any input): exact histogram select over the full lists.
// Tie order (val desc, cls asc, idx asc) == reference's stable concat order,
// encoded monotonically: val<<32 | ~((cls<<17)|idx).
__device__ __forceinline__ void inv3(const float* M, float* R) {
    float a = M[0], b = M[1], c = M[2];
    float d = M[3], e = M[4], f = M[5];
    float g = M[6], h = M[7], i = M[8];
    float A = e * i - f * h;
    float Bm = -(d * i - f * g);
    float C = d * h - e * g;
    float det = a * A + b * Bm + c * C;
    float id = 1.0f / det;
    R[0] = A * id;  R[1] = -(b * i - c * h) * id;  R[2] = (b * f - c * e) * id;
    R[3] = Bm * id; R[4] = (a * i - c * g) * id;   R[5] = -(a * f - c * d) * id;
    R[6] = C * id;  R[7] = -(a * h - b * g) * id;  R[8] = (a * e - b * d) * id;
}

__device__ __forceinline__ int vbucket(u64 k) {
    int bkt = (int)(((u32)(k >> 32) - 0x3e800000u) >> 14);
    return (bkt > 1023) ? 1023 : bkt;
}
__device__ __forceinline__ u64 repack(u64 k, int c) {
    int idx = (int)(~(u32)k) & 0x1FFFF;
    return (k & 0xFFFFFFFF00000000ULL) | (u32)(~((c << 17) | idx));
}

__global__ __launch_bounds__(1024) void k_select(
        const float* __restrict__ reg, const float* __restrict__ tmat,
        const float* __restrict__ Kmat, const float* __restrict__ img,
        float* __restrict__ out) {
    int b = blockIdx.x;
    int tid = threadIdx.x;

    __shared__ int hist[1024];
    __shared__ u64 cand[CCAP + 8];
    __shared__ u64 wtop[KTOP];
    __shared__ int sn[NCLS], shi[NCLS], spre[NCLS + 1];
    __shared__ int sB, scc;

    if (tid < NCLS) {
        sn[tid]  = g_count[b * NCLS + tid];
        shi[tid] = g_hicnt[b * NCLS + tid];
        g_count[b * NCLS + tid] = 0;      // reset for next graph replay
        g_hicnt[b * NCLS + tid] = 0;
    }
    if (tid == 0) scc = 0;
    if (tid < KTOP) wtop[tid] = 0;
    __syncthreads();

    bool hi_ok = true;
    int hitot = 0;
#pragma unroll
    for (int c = 0; c < NCLS; c++) {
        if (shi[c] > HCAP) hi_ok = false;   // overflow: hi tier incomplete
        hitot += min(shi[c], HCAP);
    }
    int m;

    if (hi_ok && hitot >= KTOP && hitot <= CCAP) {
        // ---- fast path: top-50 subset of hi tier ----
        spre[0] = 0;
        spre[1] = shi[0];
        spre[2] = shi[0] + shi[1];
        m = hitot;
#pragma unroll
        for (int c = 0; c < NCLS; c++) {
            const u64* hk = g_hikey[b * NCLS + c];
            for (int i = tid; i < shi[c]; i += 1024)
                cand[spre[c] + i] = repack(hk[i], c);
        }
        __syncthreads();
    } else {
        // ---- exact fallback: histogram select over full lists ----
        hist[tid] = 0;
        __syncthreads();
#pragma unroll
        for (int c = 0; c < NCLS; c++) {
            const u64* ck = g_ckey[b * NCLS + c];
            int n = sn[c];
            int i = tid;
            for (; i + 7 * 1024 < n; i += 8 * 1024) {
                u64 kk[8];
#pragma unroll
                for (int j = 0; j < 8; j++) kk[j] = ck[i + j * 1024];
#pragma unroll
                for (int j = 0; j < 8; j++) atomicAdd(&hist[vbucket(kk[j])], 1);
            }
            for (; i < n; i += 1024)
                atomicAdd(&hist[vbucket(ck[i])], 1);
        }
        __syncthreads();
        if (tid == 0) {
            int cum = 0, bsel = 0;
            for (int bkt = 1023; bkt >= 0; bkt--) {
                cum += hist[bkt];
                if (cum >= KTOP) { bsel = bkt; break; }
            }
            sB = bsel;
        }
        __syncthreads();
        u64 kmin = ((u64)(0x3e800000u + ((u32)sB << 14))) << 32;
#pragma unroll
        for (int c = 0; c < NCLS; c++) {
            const u64* ck = g_ckey[b * NCLS + c];
            int n = sn[c];
            for (int i = tid; i < n; i += 1024) {
                u64 k = ck[i];
                if (k >= kmin) {
                    int pos = atomicAdd(&scc, 1);
                    if (pos < CCAP) cand[pos] = repack(k, c);
                }
            }
        }
        __syncthreads();
        m = min(scc, CCAP);
    }

    // zero-pad to a multiple of 8 (pad keys = 0, never counted: real keys > 0)
    int m8 = (m + 7) & ~7;
    if (tid >= m && tid < m8) cand[tid] = 0;
    if (tid < 8) cand[m8 + tid] = 0;
    __syncthreads();

    // ---- brute-force stable rank, 8 LDS in flight per iteration ----
    if (tid < m) {
        u64 k = cand[tid];
        int rank = 0;
        for (int j = 0; j < m8; j += 8) {
            u64 c0 = cand[j + 0], c1 = cand[j + 1], c2 = cand[j + 2], c3 = cand[j + 3];
            u64 c4 = cand[j + 4], c5 = cand[j + 5], c6 = cand[j + 6], c7 = cand[j + 7];
            rank += (int)(c0 > k) + (int)(c1 > k) + (int)(c2 > k) + (int)(c3 > k)
                  + (int)(c4 > k) + (int)(c5 > k) + (int)(c6 > k) + (int)(c7 > k);
        }
        if (rank < KTOP) wtop[rank] = k;
    }
    __syncthreads();

    if (tid >= KTOP) return;

    u64 key = wtop[tid];
    float score = __uint_as_float((u32)(key >> 32));
    float* o = out + ((size_t)b * KTOP + tid) * 14;

    if (!(score > DET_THR)) {      // includes zero-padding keys
#pragma unroll
        for (int k = 0; k < 14; k++) o[k] = 0.0f;
        return;
    }

    u32 low = ~(u32)key;
    int cls = (int)(low >> 17);
    int ind = (int)(low & 0x1FFFF);
    float xs = (float)(ind % WW);
    float ys = (float)(ind / WW);

    float r8[8];
#pragma unroll
    for (int ch = 0; ch < 8; ch++)
        r8[ch] = reg[((size_t)b * 8 + ch) * HW + ind];

    float T[9], Ti[9], Kk[9], Ki[9];
#pragma unroll
    for (int k = 0; k < 9; k++) { T[k] = tmat[b * 9 + k]; Kk[k] = Kmat[b * 9 + k]; }
    inv3(T, Ti);
    inv3(Kk, Ki);

    float px = xs + r8[1];
    float py = ys + r8[2];
    float pix = Ti[0] * px + Ti[1] * py + Ti[2];
    float piy = Ti[3] * px + Ti[4] * py + Ti[5];
    float piz = Ti[6] * px + Ti[7] * py + Ti[8];

    float depth = r8[0] * 16.32f + 28.01f;
    float vx = pix * depth, vy = piy * depth, vz = piz * depth;
    float lx = Ki[0] * vx + Ki[1] * vy + Ki[2] * vz;
    float ly = Ki[3] * vx + Ki[4] * vy + Ki[5] * vz;
    float lz = Ki[6] * vx + Ki[7] * vy + Ki[8] * vz;

    float d0 = __expf(r8[3]) * c_dimref[cls][0];
    float d1 = __expf(r8[4]) * c_dimref[cls][1];
    float d2 = __expf(r8[5]) * c_dimref[cls][2];
    ly += d1 * 0.5f;

    float rays = atanf(__fdividef(lx, lz + 1e-7f));
    float al = atanf(__fdividef(r8[6], r8[7] + 1e-7f));
    al += (r8[7] >= 0.0f) ? -PI_F * 0.5f : PI_F * 0.5f;
    float roty = al + rays;
    roty = (roty > PI_F) ? roty - 2.0f * PI_F : ((roty < -PI_F) ? roty + 2.0f * PI_F : roty);
    al   = (al   > PI_F) ? al   - 2.0f * PI_F : ((al   < -PI_F) ? al   + 2.0f * PI_F : al);

    const float SX[8] = {-0.5f, 0.5f, 0.5f, 0.5f, 0.5f, -0.5f, -0.5f, -0.5f};
    const float SY[8] = {-1.0f, -1.0f, 0.0f, 0.0f, -1.0f, -1.0f, 0.0f, 0.0f};
    const float SZ[8] = {-0.5f, -0.5f, -0.5f, 0.5f, 0.5f, 0.5f, 0.5f, -0.5f};

    float sr, cr;
    __sincosf(roty, &sr, &cr);
    float umin = 3.4e38f, umax = -3.4e38f, wmin = 3.4e38f, wmax = -3.4e38f;
#pragma unroll
    for (int j = 0; j < 8; j++) {
        float cx = d0 * SX[j], cy = d1 * SY[j], cz = d2 * SZ[j];
        float wx = cr * cx + sr * cz + lx;
        float wy = cy + ly;
        float wz = -sr * cx + cr * cz + lz;
        float qx = Kk[0] * wx + Kk[1] * wy + Kk[2] * wz;
        float qy = Kk[3] * wx + Kk[4] * wy + Kk[5] * wz;
        float qz = Kk[6] * wx + Kk[7] * wy + Kk[8] * wz;
        float rq = __fdividef(1.0f, qz);
        float u = qx * rq;
        float w = qy * rq;
        umin = fminf(umin, u); umax = fmaxf(umax, u);
        wmin = fminf(wmin, w); wmax = fmaxf(wmax, w);
    }

    float Wi = img[b * 2 + 0], Hi = img[b * 2 + 1];
    float xmin = fminf(fmaxf(umin, 0.0f), Wi);
    float ymin = fminf(fmaxf(wmin, 0.0f), Hi);
    float xmax = fminf(fmaxf(umax, 0.0f), Wi);
    float ymax = fminf(fmaxf(wmax, 0.0f), Hi);

    o[0]  = (float)cls;
    o[1]  = al;
    o[2]  = xmin;
    o[3]  = ymin;
    o[4]  = xmax;
    o[5]  = ymax;
    o[6]  = d1;   // dims rolled -1: (d1, d2, d0)
    o[7]  = d2;
    o[8]  = d0;
    o[9]  = lx;
    o[10] = ly;
    o[11] = lz;
    o[12] = roty;
    o[13] = score;
}

extern "C" void kernel_launch(void* const* d_in, const int* in_sizes, int n_in,
                              void* d_out, int out_size) {
    const float* heat = (const float*)d_in[0];
    const float* reg  = (const float*)d_in[1];
    const float* tm   = (const float*)d_in[2];
    const float* Km   = (const float*)d_in[3];
    const float* img  = (const float*)d_in[4];
    float* out = (float*)d_out;

    dim3 g_nms(NYB, NPL);   // 24 x 96
    k_nms<<<g_nms, NTHR>>>(heat);
    k_select<<<BATCH, 1024>>>(reg, tm, Km, img, out);
}

// round 14
// speedup vs baseline: 1.7471x; 1.2542x over previous
#include <cuda_runtime.h>
#include <math.h>

#define BATCH 32
#define NCLS 3
#define HH 192
#define WW 640
#define HW (HH*WW)
#define NPL (BATCH*NCLS)
#define KTOP 50
#define NEG_INF -3.402823466e38f
#define PI_F 3.14159265358979f
#define DET_THR 0.25f
#define HI_THR 0.999f
#define RROWS 8
#define NYB (HH/RROWS)
#define NTHR 160
#define HCAP 1024
#define CCAP 3072

typedef unsigned long long u64;
typedef unsigned int u32;

// -------- scratch (static device globals; zero-initialized at load) --------
__device__ int g_hicnt[NPL];
__device__ u64 g_hikey[NPL][HCAP];   // ALL survivors with v >= HI_THR (tiny)

__constant__ float c_dimref[3][3] = {
    {3.88f, 1.63f, 1.53f},
    {0.84f, 1.76f, 0.66f},
    {1.78f, 1.52f, 1.78f}};

__device__ __forceinline__ float max3(float a, float b, float c) {
    return fmaxf(a, fmaxf(b, c));
}
__device__ __forceinline__ u64 pack_key(float v, int idx) {
    return ((u64)__float_as_uint(v) << 32) | (u32)(~idx);
}
// final key: val<<32 | ~((cls<<17)|idx) — monotonic in (val desc, cls asc, idx asc)
__device__ __forceinline__ u64 repack(u64 k, int c) {
    int idx = (int)(~(u32)k) & 0x1FFFF;
    return (k & 0xFFFFFFFF00000000ULL) | (u32)(~((c << 17) | idx));
}

// -------- pass 1: 3x3 NMS, load-all-then-compute (MLP=10) --------
// NO full candidate list anymore: only hi-tier survivors (v >= HI_THR,
// ~122/plane) are stored, via rare direct atomics. The exact fallback for
// adversarial inputs recomputes NMS inside k_select.
__global__ __launch_bounds__(NTHR) void k_nms(const float* __restrict__ heat) {
    int plane = blockIdx.y;
    int tid = threadIdx.x;
    int warp = tid >> 5, lane = tid & 31;
    int xb = warp * 128 + lane * 4;
    int y0 = blockIdx.x * RROWS;
    const float* p = heat + (size_t)plane * HW + xb;

    const float4 NEG4 = make_float4(NEG_INF, NEG_INF, NEG_INF, NEG_INF);

    __shared__ float sL[5][RROWS];
    __shared__ float sR[5][RROWS];

    float4 r[RROWS + 2];
    const float* rp = p + (y0 - 1) * WW;
#pragma unroll
    for (int k = 0; k < RROWS + 2; k++) {
        int y = y0 - 1 + k;
        r[k] = (y >= 0 && y < HH) ? *(const float4*)(rp + k * WW) : NEG4;
    }

    float4 cm[RROWS];
#pragma unroll
    for (int i = 0; i < RROWS; i++) {
        cm[i].x = max3(r[i].x, r[i+1].x, r[i+2].x);
        cm[i].y = max3(r[i].y, r[i+1].y, r[i+2].y);
        cm[i].z = max3(r[i].z, r[i+1].z, r[i+2].z);
        cm[i].w = max3(r[i].w, r[i+1].w, r[i+2].w);
    }

    if (lane == 31) {
#pragma unroll
        for (int i = 0; i < RROWS; i++) sL[warp][i] = cm[i].w;
    }
    if (lane == 0) {
#pragma unroll
        for (int i = 0; i < RROWS; i++) sR[warp][i] = cm[i].x;
    }
    __syncthreads();

#pragma unroll
    for (int i = 0; i < RROWS; i++) {
        float left = __shfl_up_sync(0xffffffffu, cm[i].w, 1);
        if (lane == 0) left = (warp > 0) ? sL[warp - 1][i] : NEG_INF;
        float right = __shfl_down_sync(0xffffffffu, cm[i].x, 1);
        if (lane == 31) right = (warp < 4) ? sR[warp + 1][i] : NEG_INF;

        float h0 = max3(left,    cm[i].x, cm[i].y);
        float h1 = max3(cm[i].x, cm[i].y, cm[i].z);
        float h2 = max3(cm[i].y, cm[i].z, cm[i].w);
        float h3 = max3(cm[i].z, cm[i].w, right);

        float4 b = r[i + 1];
        int bi = (y0 + i) * WW + xb;
        // hi-tier survivors only (expected ~5 per block -> atomics are rare)
        if (h0 == b.x && b.x >= HI_THR) {
            int hp = atomicAdd(&g_hicnt[plane], 1);
            if (hp < HCAP) g_hikey[plane][hp] = pack_key(b.x, bi);
        }
        if (h1 == b.y && b.y >= HI_THR) {
            int hp = atomicAdd(&g_hicnt[plane], 1);
            if (hp < HCAP) g_hikey[plane][hp] = pack_key(b.y, bi + 1);
        }
        if (h2 == b.z && b.z >= HI_THR) {
            int hp = atomicAdd(&g_hicnt[plane], 1);
            if (hp < HCAP) g_hikey[plane][hp] = pack_key(b.z, bi + 2);
        }
        if (h3 == b.w && b.w >= HI_THR) {
            int hp = atomicAdd(&g_hicnt[plane], 1);
            if (hp < HCAP) g_hikey[plane][hp] = pack_key(b.w, bi + 3);
        }
    }
}

// -------- pass 2: per-batch top-50 + detection math --------
// Fast path: if >=KTOP hi-tier keys exist (no overflow), top-50 is contained
// in the hi tier (it holds ALL survivors with v >= HI_THR).
// Fallback (any input, exact, slow): recompute NMS from the heatmap with a
// histogram threshold select. Tie order (val desc, cls asc, idx asc) ==
// reference's stable concat order, encoded monotonically in the u64 key.
__device__ __forceinline__ void inv3(const float* M, float* R) {
    float a = M[0], b = M[1], c = M[2];
    float d = M[3], e = M[4], f = M[5];
    float g = M[6], h = M[7], i = M[8];
    float A = e * i - f * h;
    float Bm = -(d * i - f * g);
    float C = d * h - e * g;
    float det = a * A + b * Bm + c * C;
    float id = 1.0f / det;
    R[0] = A * id;  R[1] = -(b * i - c * h) * id;  R[2] = (b * f - c * e) * id;
    R[3] = Bm * id; R[4] = (a * i - c * g) * id;   R[5] = -(a * f - c * d) * id;
    R[6] = C * id;  R[7] = -(a * h - b * g) * id;  R[8] = (a * e - b * d) * id;
}
__device__ __forceinline__ int vbucket_bits(u32 vb) {
    int bkt = (int)((vb - 0x3e800000u) >> 14);
    return (bkt > 1023) ? 1023 : bkt;
}
// exact reference NMS test for one pixel (bounds-aware 3x3 max, incl self)
__device__ __forceinline__ bool nms_keep(const float* p, int idx, float v) {
    int y = idx / WW, x = idx - y * WW;
    float hmax = v;
    for (int dy = -1; dy <= 1; dy++) {
        int yy = y + dy;
        if (yy < 0 || yy >= HH) continue;
        for (int dx = -1; dx <= 1; dx++) {
            int xx = x + dx;
            if (xx < 0 || xx >= WW) continue;
            hmax = fmaxf(hmax, __ldg(p + yy * WW + xx));
        }
    }
    return hmax == v;
}

__global__ __launch_bounds__(1024) void k_select(
        const float* __restrict__ heat,
        const float* __restrict__ reg, const float* __restrict__ tmat,
        const float* __restrict__ Kmat, const float* __restrict__ img,
        float* __restrict__ out) {
    int b = blockIdx.x;
    int tid = threadIdx.x;

    __shared__ int hist[1024];
    __shared__ u64 cand[CCAP];
    __shared__ u64 wtop[KTOP];
    __shared__ int shi[NCLS], spre[NCLS + 1];
    __shared__ int sB, scc;

    if (tid < NCLS) {
        shi[tid] = g_hicnt[b * NCLS + tid];
        g_hicnt[b * NCLS + tid] = 0;      // reset for next graph replay
    }
    if (tid == 0) scc = 0;
    if (tid < KTOP) wtop[tid] = 0;
    __syncthreads();

    bool hi_ok = true;
    int hitot = 0;
#pragma unroll
    for (int c = 0; c < NCLS; c++) {
        if (shi[c] > HCAP) hi_ok = false;   // overflow: hi tier incomplete
        hitot += min(shi[c], HCAP);
    }
    int m;

    if (hi_ok && hitot >= KTOP && hitot <= CCAP) {
        // ---- fast path: top-50 subset of hi tier ----
        spre[0] = 0;
        spre[1] = shi[0];
        spre[2] = shi[0] + shi[1];
        m = hitot;
#pragma unroll
        for (int c = 0; c < NCLS; c++) {
            const u64* hk = g_hikey[b * NCLS + c];
            for (int i = tid; i < shi[c]; i += 1024)
                cand[spre[c] + i] = repack(hk[i], c);
        }
        __syncthreads();
    } else {
        // ---- exact fallback: recompute NMS + histogram select from heat ----
        hist[tid] = 0;
        __syncthreads();
#pragma unroll
        for (int c = 0; c < NCLS; c++) {
            const float* p = heat + (size_t)(b * NCLS + c) * HW;
            for (int i = tid; i < HW; i += 1024) {
                float v = __ldg(p + i);
                if (v > DET_THR && nms_keep(p, i, v))
                    atomicAdd(&hist[vbucket_bits(__float_as_uint(v))], 1);
            }
        }
        __syncthreads();
        if (tid == 0) {
            int cum = 0, bsel = 0;
            for (int bkt = 1023; bkt >= 0; bkt--) {
                cum += hist[bkt];
                if (cum >= KTOP) { bsel = bkt; break; }
            }
            sB = bsel;
        }
        __syncthreads();
        u32 thr_bits = 0x3e800000u + ((u32)sB << 14);
#pragma unroll
        for (int c = 0; c < NCLS; c++) {
            const float* p = heat + (size_t)(b * NCLS + c) * HW;
            for (int i = tid; i < HW; i += 1024) {
                float v = __ldg(p + i);
                if (v > DET_THR && __float_as_uint(v) >= thr_bits && nms_keep(p, i, v)) {
                    int pos = atomicAdd(&scc, 1);
                    if (pos < CCAP)
                        cand[pos] = ((u64)__float_as_uint(v) << 32)
                                  | (u32)(~((c << 17) | i));
                }
            }
        }
        __syncthreads();
        m = min(scc, CCAP);
    }

    // ---- brute-force stable rank among m candidates ----
    if (tid < m) {
        u64 k = cand[tid];
        int rank = 0;
        for (int j = 0; j < m; j++) rank += (cand[j] > k);
        if (rank < KTOP) wtop[rank] = k;
    }
    __syncthreads();

    if (tid >= KTOP) return;

    u64 key = wtop[tid];
    float score = __uint_as_float((u32)(key >> 32));
    float* o = out + ((size_t)b * KTOP + tid) * 14;

    if (!(score > DET_THR)) {      // includes zero-padding keys
#pragma unroll
        for (int k = 0; k < 14; k++) o[k] = 0.0f;
        return;
    }

    u32 low = ~(u32)key;
    int cls = (int)(low >> 17);
    int ind = (int)(low & 0x1FFFF);
    float xs = (float)(ind % WW);
    float ys = (float)(ind / WW);

    float r8[8];
#pragma unroll
    for (int ch = 0; ch < 8; ch++)
        r8[ch] = reg[((size_t)b * 8 + ch) * HW + ind];

    float T[9], Ti[9], Kk[9], Ki[9];
#pragma unroll
    for (int k = 0; k < 9; k++) { T[k] = tmat[b * 9 + k]; Kk[k] = Kmat[b * 9 + k]; }
    inv3(T, Ti);
    inv3(Kk, Ki);

    float px = xs + r8[1];
    float py = ys + r8[2];
    float pix = Ti[0] * px + Ti[1] * py + Ti[2];
    float piy = Ti[3] * px + Ti[4] * py + Ti[5];
    float piz = Ti[6] * px + Ti[7] * py + Ti[8];

    float depth = r8[0] * 16.32f + 28.01f;
    float vx = pix * depth, vy = piy * depth, vz = piz * depth;
    float lx = Ki[0] * vx + Ki[1] * vy + Ki[2] * vz;
    float ly = Ki[3] * vx + Ki[4] * vy + Ki[5] * vz;
    float lz = Ki[6] * vx + Ki[7] * vy + Ki[8] * vz;

    float d0 = __expf(r8[3]) * c_dimref[cls][0];
    float d1 = __expf(r8[4]) * c_dimref[cls][1];
    float d2 = __expf(r8[5]) * c_dimref[cls][2];
    ly += d1 * 0.5f;

    float rays = atanf(__fdividef(lx, lz + 1e-7f));
    float al = atanf(__fdividef(r8[6], r8[7] + 1e-7f));
    al += (r8[7] >= 0.0f) ? -PI_F * 0.5f : PI_F * 0.5f;
    float roty = al + rays;
    roty = (roty > PI_F) ? roty - 2.0f * PI_F : ((roty < -PI_F) ? roty + 2.0f * PI_F : roty);
    al   = (al   > PI_F) ? al   - 2.0f * PI_F : ((al   < -PI_F) ? al   + 2.0f * PI_F : al);

    const float SX[8] = {-0.5f, 0.5f, 0.5f, 0.5f, 0.5f, -0.5f, -0.5f, -0.5f};
    const float SY[8] = {-1.0f, -1.0f, 0.0f, 0.0f, -1.0f, -1.0f, 0.0f, 0.0f};
    const float SZ[8] = {-0.5f, -0.5f, -0.5f, 0.5f, 0.5f, 0.5f, 0.5f, -0.5f};

    float sr, cr;
    __sincosf(roty, &sr, &cr);
    float umin = 3.4e38f, umax = -3.4e38f, wmin = 3.4e38f, wmax = -3.4e38f;
#pragma unroll
    for (int j = 0; j < 8; j++) {
        float cx = d0 * SX[j], cy = d1 * SY[j], cz = d2 * SZ[j];
        float wx = cr * cx + sr * cz + lx;
        float wy = cy + ly;
        float wz = -sr * cx + cr * cz + lz;
        float qx = Kk[0] * wx + Kk[1] * wy + Kk[2] * wz;
        float qy = Kk[3] * wx + Kk[4] * wy + Kk[5] * wz;
        float qz = Kk[6] * wx + Kk[7] * wy + Kk[8] * wz;
        float rq = __fdividef(1.0f, qz);
        float u = qx * rq;
        float w = qy * rq;
        umin = fminf(umin, u); umax = fmaxf(umax, u);
        wmin = fminf(wmin, w); wmax = fmaxf(wmax, w);
    }

    float Wi = img[b * 2 + 0], Hi = img[b * 2 + 1];
    float xmin = fminf(fmaxf(umin, 0.0f), Wi);
    float ymin = fminf(fmaxf(wmin, 0.0f), Hi);
    float xmax = fminf(fmaxf(umax, 0.0f), Wi);
    float ymax = fminf(fmaxf(wmax, 0.0f), Hi);

    o[0]  = (float)cls;
    o[1]  = al;
    o[2]  = xmin;
    o[3]  = ymin;
    o[4]  = xmax;
    o[5]  = ymax;
    o[6]  = d1;   // dims rolled -1: (d1, d2, d0)
    o[7]  = d2;
    o[8]  = d0;
    o[9]  = lx;
    o[10] = ly;
    o[11] = lz;
    o[12] = roty;
    o[13] = score;
}

extern "C" void kernel_launch(void* const* d_in, const int* in_sizes, int n_in,
                              void* d_out, int out_size) {
    const float* heat = (const float*)d_in[0];
    const float* reg  = (const float*)d_in[1];
    const float* tm   = (const float*)d_in[2];
    const float* Km   = (const float*)d_in[3];
    const float* img  = (const float*)d_in[4];
    float* out = (float*)d_out;

    dim3 g_nms(NYB, NPL);   // 24 x 96
    k_nms<<<g_nms, NTHR>>>(heat);
    k_select<<<BATCH, 1024>>>(heat, reg, tm, Km, img, out);
}